// round 14
// baseline (speedup 1.0000x reference)
#include <cuda_runtime.h>
#include <mma.h>
#include <cstdint>
#include <cstddef>

using namespace nvcuda;

#define NH 50000
#define NF 200000
#define HDIM 128
#define NUM_BLOCKS 2
#define TILE 2048

#define E_SENDS_MAX 1000000
#define E_PREC_MAX  2000000

// fused-kernel smem layout (floats): As0[128*132] As1[128*132] Ax[128*36] Bs[128*36]
#define AS_LD 132
#define AX_LD 36
#define SM_AS0 0
#define SM_AS1 (128 * AS_LD)
#define SM_AX  (2 * 128 * AS_LD)
#define SM_BS  (2 * 128 * AS_LD + 128 * AX_LD)
#define SM_FLOATS (2 * 128 * AS_LD + 2 * 128 * AX_LD)
#define SM_BYTES (SM_FLOATS * 4)

// ---------------- scratch (device globals; no allocations allowed) ----------------
__device__ float g_f_buf1[(size_t)NF * HDIM];
__device__ float g_f_buf2[(size_t)NF * HDIM];
__device__ float g_h_buf1[(size_t)NH * HDIM];
__device__ float g_h_buf2[(size_t)NH * HDIM];
__device__ float g_Bt[2 * 2 * 128 * 384];       // [blk][type][n=128][k=384] K-major
__device__ float g_stats[4 * HDIM];

// CSR scratch. deg4/next4 concatenated: [sends NF][prec NF][rev NH][reach NH].
// INVARIANT: deg4 all-zero at entry (zero-init at load; re-zeroed by scan_fix).
__device__ int g_deg4[2 * NF + 2 * NH];
__device__ int g_next4[2 * NF + 2 * NH];
__device__ int g_ptr_sends[NF + 1];
__device__ int g_ptr_prec[NF + 1];
__device__ int g_ptr_rev[NH + 1];
__device__ int g_ptr_reach[NH + 1];
__device__ int g_part[4 * 128];
__device__ int g_col_sends[E_SENDS_MAX];
__device__ int g_col_prec[E_PREC_MAX];
__device__ int g_col_rev[E_SENDS_MAX];
__device__ int g_col_reach[E_SENDS_MAX];

// ---------------- cache-hinted accessors ----------------
__device__ __forceinline__ float4 ldcs4(const float* p) {
    float4 v;
    asm volatile("ld.global.cs.v4.f32 {%0,%1,%2,%3}, [%4];"
                 : "=f"(v.x), "=f"(v.y), "=f"(v.z), "=f"(v.w) : "l"(p));
    return v;
}
__device__ __forceinline__ float ldcs1(const float* p) {
    float v;
    asm volatile("ld.global.cs.f32 %0, [%1];" : "=f"(v) : "l"(p));
    return v;
}

__device__ __forceinline__ int type_n(int t) { return (t < 2) ? NF : NH; }
__device__ __forceinline__ int type_off(int t) {
    return (t == 0) ? 0 : (t == 1) ? NF : (t == 2) ? 2 * NF : 2 * NF + NH;
}

// ---------------- CSR build (4 launches; all types via blockIdx.y) ----------------

__global__ void hist_all(const int* __restrict__ e0, int E0, const int* __restrict__ e1, int E1,
                         const int* __restrict__ e2, int E2, const int* __restrict__ e3, int E3,
                         int* __restrict__ deg4) {
    int t = blockIdx.y;
    const int* ei = (t == 0) ? e0 : (t == 1) ? e1 : (t == 2) ? e2 : e3;
    int E = (t == 0) ? E0 : (t == 1) ? E1 : (t == 2) ? E2 : E3;
    int e = blockIdx.x * blockDim.x + threadIdx.x;
    if (e < E) atomicAdd(&deg4[type_off(t) + ei[E + e]], 1);
}

__global__ void scan_tiles(const int* __restrict__ deg4,
                           int* __restrict__ p0, int* __restrict__ p1,
                           int* __restrict__ p2, int* __restrict__ p3,
                           int* __restrict__ part) {
    int t = blockIdx.y;
    int n = type_n(t);
    int tiles = (n + TILE - 1) / TILE;
    if ((int)blockIdx.x >= tiles) return;
    const int* deg = deg4 + type_off(t);
    int* ptr = (t == 0) ? p0 : (t == 1) ? p1 : (t == 2) ? p2 : p3;
    __shared__ int sh[16];
    int base = blockIdx.x * TILE + threadIdx.x * 8;
    int v[8];
    int ls = 0;
#pragma unroll
    for (int j = 0; j < 8; j++) { v[j] = (base + j < n) ? deg[base + j] : 0; ls += v[j]; }
    int lane = threadIdx.x & 31, wid = threadIdx.x >> 5;
    int s = ls;
#pragma unroll
    for (int d = 1; d < 32; d <<= 1) {
        int x = __shfl_up_sync(0xffffffff, s, d);
        if (lane >= d) s += x;
    }
    if (lane == 31) sh[wid] = s;
    __syncthreads();
    if (threadIdx.x == 0) {
        int run = 0;
        for (int i = 0; i < 8; i++) { int x = sh[i]; sh[i] = run; run += x; }
        sh[8] = run;
    }
    __syncthreads();
    int run = sh[wid] + s - ls;
#pragma unroll
    for (int j = 0; j < 8; j++) {
        if (base + j < n) ptr[base + j] = run;
        run += v[j];
    }
    if (threadIdx.x == 0) part[t * 128 + blockIdx.x] = sh[8];
}

__global__ void scan_fix(int* __restrict__ p0, int* __restrict__ p1,
                         int* __restrict__ p2, int* __restrict__ p3,
                         int* __restrict__ next4, const int* __restrict__ part,
                         int* __restrict__ deg4) {
    int t = blockIdx.y;
    int n = type_n(t);
    int tiles = (n + TILE - 1) / TILE;
    if ((int)blockIdx.x >= tiles) return;
    int* ptr = (t == 0) ? p0 : (t == 1) ? p1 : (t == 2) ? p2 : p3;
    int* nxt = next4 + type_off(t);

    __shared__ int spart[128];
    __shared__ int s_off, s_tot;
    if (threadIdx.x < 128)
        spart[threadIdx.x] = (threadIdx.x < tiles) ? part[t * 128 + threadIdx.x] : 0;
    __syncthreads();
    if (threadIdx.x == 0) {
        int off = 0, tot = 0;
        for (int i = 0; i < tiles; i++) {
            if (i < (int)blockIdx.x) off += spart[i];
            tot += spart[i];
        }
        s_off = off; s_tot = tot;
    }
    __syncthreads();
    int off = s_off;

    int base = blockIdx.x * TILE + threadIdx.x * 8;
#pragma unroll
    for (int j = 0; j < 8; j++) {
        int idx = base + j;
        if (idx < n) {
            int v = ptr[idx] + off;
            ptr[idx] = v;
            nxt[idx] = v;
            deg4[type_off(t) + idx] = 0;
        }
    }
    if (blockIdx.x == 0 && threadIdx.x == 0) ptr[n] = s_tot;
}

__global__ void fill_all(const int* __restrict__ e0, int E0, const int* __restrict__ e1, int E1,
                         const int* __restrict__ e2, int E2, const int* __restrict__ e3, int E3,
                         int* __restrict__ next4,
                         int* __restrict__ c0, int* __restrict__ c1,
                         int* __restrict__ c2, int* __restrict__ c3) {
    int t = blockIdx.y;
    const int* ei = (t == 0) ? e0 : (t == 1) ? e1 : (t == 2) ? e2 : e3;
    int E = (t == 0) ? E0 : (t == 1) ? E1 : (t == 2) ? E2 : E3;
    int* col = (t == 0) ? c0 : (t == 1) ? c1 : (t == 2) ? c2 : c3;
    int* nxt = next4 + type_off(t);
    int e = blockIdx.x * blockDim.x + threadIdx.x;
    if (e >= E) return;
    int s = ei[e];
    int d = ei[E + e];
    int pos = atomicAdd(&nxt[d], 1);
    col[pos] = s;
}

// ---------------- weights ----------------
__global__ void prep_weights(const float* __restrict__ Wl, const float* __restrict__ Wr,
                             float* __restrict__ Bt) {
    int i = blockIdx.x * blockDim.x + threadIdx.x;
    const int total = 2 * 2 * 128 * 384;
    if (i >= total) return;
    int k = i % 384;
    int n = (i / 384) & 127;
    int t = (i / (384 * 128)) & 1;
    int b = i / (384 * 128 * 2);
    int ta = t ? 1 : 0, tb = t ? 3 : 2;
    int seg = k >> 7, kk = k & 127;
    float v;
    if (seg == 0)      v = Wl[(((size_t)b * 4 + ta) * 128 + n) * 128 + kk];
    else if (seg == 1) v = Wl[(((size_t)b * 4 + tb) * 128 + n) * 128 + kk];
    else               v = Wr[(((size_t)b * 4 + ta) * 128 + n) * 128 + kk]
                         + Wr[(((size_t)b * 4 + tb) * 128 + n) * 128 + kk];
    Bt[i] = 0.5f * v;
}

// ---------------- fused SAGE: gather (2 types) into smem + WMMA tf32 GEMM ----------------
// out[r][o] = sum_k Aeff[r][k]*Bt[o][k]; Aeff K-segs: mean0 | mean1 | x_dst.
// Block = 128 dst rows, 256 threads. Means computed straight into smem (no global agg).
__device__ __forceinline__ void gather_row_sm(const float* __restrict__ src,
                                              const int* __restrict__ ptr,
                                              const int* __restrict__ col,
                                              int gr, int lane, float* __restrict__ dst) {
    const int s0 = __ldg(&ptr[gr]);
    const int s1 = __ldg(&ptr[gr + 1]);
    float4 a0 = make_float4(0.f, 0.f, 0.f, 0.f);
    float4 a1 = make_float4(0.f, 0.f, 0.f, 0.f);
    float4 a2 = make_float4(0.f, 0.f, 0.f, 0.f);
    float4 a3 = make_float4(0.f, 0.f, 0.f, 0.f);
    int e = s0;
    for (; e + 3 < s1; e += 4) {
        int iA = __ldg(&col[e]);
        int iB = __ldg(&col[e + 1]);
        int iC = __ldg(&col[e + 2]);
        int iD = __ldg(&col[e + 3]);
        float4 vA = *(const float4*)(src + (size_t)iA * HDIM + lane * 4);
        float4 vB = *(const float4*)(src + (size_t)iB * HDIM + lane * 4);
        float4 vC = *(const float4*)(src + (size_t)iC * HDIM + lane * 4);
        float4 vD = *(const float4*)(src + (size_t)iD * HDIM + lane * 4);
        a0.x += vA.x; a0.y += vA.y; a0.z += vA.z; a0.w += vA.w;
        a1.x += vB.x; a1.y += vB.y; a1.z += vB.z; a1.w += vB.w;
        a2.x += vC.x; a2.y += vC.y; a2.z += vC.z; a2.w += vC.w;
        a3.x += vD.x; a3.y += vD.y; a3.z += vD.z; a3.w += vD.w;
    }
    for (; e < s1; e++) {
        int iA = __ldg(&col[e]);
        float4 vA = *(const float4*)(src + (size_t)iA * HDIM + lane * 4);
        a0.x += vA.x; a0.y += vA.y; a0.z += vA.z; a0.w += vA.w;
    }
    float inv = 1.0f / (float)max(s1 - s0, 1);
    float4 r;
    r.x = (a0.x + a1.x + a2.x + a3.x) * inv;
    r.y = (a0.y + a1.y + a2.y + a3.y) * inv;
    r.z = (a0.z + a1.z + a2.z + a3.z) * inv;
    r.w = (a0.w + a1.w + a2.w + a3.w) * inv;
    *(float4*)(dst + lane * 4) = r;
}

__global__ __launch_bounds__(256) void sage_fused(
    const float* __restrict__ src0, const int* __restrict__ ptr0, const int* __restrict__ col0,
    const float* __restrict__ src1, const int* __restrict__ ptr1, const int* __restrict__ col1,
    const float* __restrict__ xdst, const float* __restrict__ Bt,
    float* __restrict__ out, int nrows)
{
    extern __shared__ float sm[];
    float* As0 = sm + SM_AS0;
    float* As1 = sm + SM_AS1;
    float* Ax  = sm + SM_AX;
    float* Bs  = sm + SM_BS;

    const int tid = threadIdx.x;
    const int lane = tid & 31, wid = tid >> 5;
    const int row0 = blockIdx.x * 128;

    // ---- phase 1: gather both edge-type means into smem ----
#pragma unroll 1
    for (int i = 0; i < 16; i++) {
        int r = i * 8 + wid;          // 0..127
        int gr = row0 + r;
        if (gr < nrows) {
            gather_row_sm(src0, ptr0, col0, gr, lane, As0 + r * AS_LD);
            gather_row_sm(src1, ptr1, col1, gr, lane, As1 + r * AS_LD);
        }
    }
    __syncthreads();

    // ---- phase 2: WMMA tf32 GEMM ----
    const int wrow_l = wid * 16;
    const int wrow_g = row0 + wrow_l;
    const bool wvalid = wrow_g < nrows;   // nrows multiple of 16 -> strip all-valid

    wmma::fragment<wmma::accumulator, 16, 16, 8, float> acc[8];
#pragma unroll
    for (int nt = 0; nt < 8; nt++) wmma::fill_fragment(acc[nt], 0.0f);

    for (int chunk = 0; chunk < 12; chunk++) {
        const int kbase = chunk * 32;
        const int koff = (chunk & 3) * 32;

        // stage B chunk (128n x 32k)
#pragma unroll
        for (int i = 0; i < 4; i++) {
            int idx = tid + i * 256;
            int n = idx >> 3, q = idx & 7;
            *(float4*)&Bs[n * AX_LD + q * 4] =
                *(const float4*)(Bt + (size_t)n * 384 + kbase + q * 4);
        }
        // stage x chunk when needed
        if (chunk >= 8) {
#pragma unroll
            for (int i = 0; i < 4; i++) {
                int idx = tid + i * 256;
                int r = idx >> 3, q = idx & 7;
                int gr = row0 + r;
                float4 v = make_float4(0.f, 0.f, 0.f, 0.f);
                if (gr < nrows)
                    v = *(const float4*)(xdst + (size_t)gr * HDIM + koff + q * 4);
                *(float4*)&Ax[r * AX_LD + q * 4] = v;
            }
        }
        __syncthreads();

        if (wvalid) {
#pragma unroll
            for (int kk = 0; kk < 4; kk++) {
                wmma::fragment<wmma::matrix_a, 16, 16, 8, wmma::precision::tf32,
                               wmma::row_major> a;
                if (chunk < 4)
                    wmma::load_matrix_sync(a, As0 + wrow_l * AS_LD + koff + kk * 8, AS_LD);
                else if (chunk < 8)
                    wmma::load_matrix_sync(a, As1 + wrow_l * AS_LD + koff + kk * 8, AS_LD);
                else
                    wmma::load_matrix_sync(a, Ax + wrow_l * AX_LD + kk * 8, AX_LD);
#pragma unroll
                for (int t = 0; t < a.num_elements; t++)
                    a.x[t] = wmma::__float_to_tf32(a.x[t]);
#pragma unroll
                for (int nt = 0; nt < 8; nt++) {
                    wmma::fragment<wmma::matrix_b, 16, 16, 8, wmma::precision::tf32,
                                   wmma::col_major> b;
                    wmma::load_matrix_sync(b, Bs + nt * 16 * AX_LD + kk * 8, AX_LD);
#pragma unroll
                    for (int t = 0; t < b.num_elements; t++)
                        b.x[t] = wmma::__float_to_tf32(b.x[t]);
                    wmma::mma_sync(acc[nt], a, b, acc[nt]);
                }
            }
        }
        __syncthreads();
    }

    if (wvalid) {
#pragma unroll
        for (int nt = 0; nt < 8; nt++)
            wmma::store_matrix_sync(out + (size_t)wrow_g * HDIM + nt * 16, acc[nt],
                                    HDIM, wmma::mem_row_major);
    }
}

// ---------------- BN + LeakyReLU ----------------
__global__ void bn_stats(const float* __restrict__ v, int n,
                         float* __restrict__ sum, float* __restrict__ sq) {
    int c = threadIdx.x & 127;
    int sub = threadIdx.x >> 7;
    float s = 0.f, s2 = 0.f;
    for (int r = blockIdx.x * 2 + sub; r < n; r += gridDim.x * 2) {
        float x = ldcs1(v + (size_t)r * HDIM + c);
        s += x;
        s2 += x * x;
    }
    __shared__ float sh[256], sh2[256];
    sh[threadIdx.x] = s;
    sh2[threadIdx.x] = s2;
    __syncthreads();
    if (sub == 0) {
        atomicAdd(&sum[c], sh[c] + sh[c + 128]);
        atomicAdd(&sq[c], sh2[c] + sh2[c + 128]);
    }
}

__global__ void bn_apply(const float* __restrict__ in, float* __restrict__ out, int n,
                         const float* __restrict__ sum, const float* __restrict__ sq,
                         const float* __restrict__ gamma, const float* __restrict__ beta) {
    size_t i4 = (size_t)blockIdx.x * blockDim.x + threadIdx.x;
    size_t total4 = (size_t)n * (HDIM / 4);
    if (i4 >= total4) return;
    int c4 = (int)(i4 & 31);
    float N = (float)n;
    float4 v = ldcs4(in + i4 * 4);
    float o[4];
#pragma unroll
    for (int j = 0; j < 4; j++) {
        int c = c4 * 4 + j;
        float mu = sum[c] / N;
        float var = sq[c] / N - mu * mu;
        float rstd = rsqrtf(var + 1e-5f);
        float x = (((&v.x)[j]) - mu) * rstd * gamma[c] + beta[c];
        o[j] = x >= 0.f ? x : 0.01f * x;
    }
    *(float4*)(out + i4 * 4) = make_float4(o[0], o[1], o[2], o[3]);
}

// ---------------- host ----------------
static inline void* sym(const void* s) {
    void* p = 0;
    cudaGetSymbolAddress(&p, s);
    return p;
}

extern "C" void kernel_launch(void* const* d_in, const int* in_sizes, int n_in,
                              void* d_out, int out_size) {
    const float* x_host = (const float*)d_in[0];
    const float* x_flow = (const float*)d_in[1];
    const int* ei_sends = (const int*)d_in[2];
    const int* ei_rev   = (const int*)d_in[3];
    const int* ei_prec  = (const int*)d_in[4];
    const int* ei_reach = (const int*)d_in[5];
    const float* W_l = (const float*)d_in[6];
    const float* W_r = (const float*)d_in[8];
    const float* bn_gamma = (const float*)d_in[9];
    const float* bn_beta  = (const float*)d_in[10];
    float* out = (float*)d_out;

    int E_sends = in_sizes[2] / 2;
    int E_rev   = in_sizes[3] / 2;
    int E_prec  = in_sizes[4] / 2;
    int E_reach = in_sizes[5] / 2;

    float* f_buf1 = (float*)sym(g_f_buf1);
    float* f_buf2 = (float*)sym(g_f_buf2);
    float* h_buf1 = (float*)sym(g_h_buf1);
    float* h_buf2 = (float*)sym(g_h_buf2);
    float* Bt    = (float*)sym(g_Bt);
    float* stats = (float*)sym(g_stats);

    int* deg4      = (int*)sym(g_deg4);
    int* next4     = (int*)sym(g_next4);
    int* ptr_sends = (int*)sym(g_ptr_sends);
    int* ptr_prec  = (int*)sym(g_ptr_prec);
    int* ptr_rev   = (int*)sym(g_ptr_rev);
    int* ptr_reach = (int*)sym(g_ptr_reach);
    int* part      = (int*)sym(g_part);
    int* col_sends = (int*)sym(g_col_sends);
    int* col_prec  = (int*)sym(g_col_prec);
    int* col_rev   = (int*)sym(g_col_rev);
    int* col_reach = (int*)sym(g_col_reach);

    static bool attr_set = false;
    if (!attr_set) {
        cudaFuncSetAttribute(sage_fused, cudaFuncAttributeMaxDynamicSharedMemorySize,
                             SM_BYTES);
        attr_set = true;
    }

    // ---- CSR build: 4 launches (deg4 zero on entry; scan_fix restores it) ----
    int Emax = max(max(E_sends, E_prec), max(E_rev, E_reach));
    dim3 egrid((Emax + 255) / 256, 4);
    dim3 sgrid((NF + TILE - 1) / TILE, 4);

    hist_all<<<egrid, 256>>>(ei_sends, E_sends, ei_prec, E_prec,
                             ei_rev, E_rev, ei_reach, E_reach, deg4);
    scan_tiles<<<sgrid, 256>>>(deg4, ptr_sends, ptr_prec, ptr_rev, ptr_reach, part);
    scan_fix<<<sgrid, 256>>>(ptr_sends, ptr_prec, ptr_rev, ptr_reach, next4, part, deg4);
    fill_all<<<egrid, 256>>>(ei_sends, E_sends, ei_prec, E_prec,
                             ei_rev, E_rev, ei_reach, E_reach, next4,
                             col_sends, col_prec, col_rev, col_reach);
    {
        int tot = 2 * 2 * 128 * 384;
        prep_weights<<<(tot + 255) / 256, 256>>>(W_l, W_r, Bt);
    }

    const int grid_f = (NF + 127) / 128;
    const int grid_h = (NH + 127) / 128;

    const float* h_cur = x_host;
    const float* f_cur = x_flow;

    for (int blk = 0; blk < NUM_BLOCKS; blk++) {
        float* f_next = blk == 0 ? f_buf1 : f_buf2;
        float* h_next = blk == 0 ? h_buf1 : h_buf2;

        const float* Bf = Bt + (size_t)(blk * 2 + 0) * 128 * 384;
        const float* Bh = Bt + (size_t)(blk * 2 + 1) * 128 * 384;

        // fused gather+GEMM (no global agg intermediates)
        sage_fused<<<grid_f, 256, SM_BYTES>>>(h_cur, ptr_sends, col_sends,
                                              f_cur, ptr_prec, col_prec,
                                              f_cur, Bf, f_next, NF);
        sage_fused<<<grid_h, 256, SM_BYTES>>>(f_cur, ptr_rev, col_rev,
                                              f_cur, ptr_reach, col_reach,
                                              h_cur, Bh, h_next, NH);

        cudaMemsetAsync(stats, 0, 4 * HDIM * 4);
        bn_stats<<<1024, 256>>>(h_next, NH, stats, stats + HDIM);
        bn_stats<<<1024, 256>>>(f_next, NF, stats + 2 * HDIM, stats + 3 * HDIM);

        const float* gamma = bn_gamma + blk * HDIM;
        const float* beta  = bn_beta + blk * HDIM;
        float* h_out = (blk == NUM_BLOCKS - 1) ? out : h_next;
        float* f_out = (blk == NUM_BLOCKS - 1) ? (out + (size_t)NH * HDIM) : f_next;
        {
            size_t tot4 = (size_t)NH * (HDIM / 4);
            bn_apply<<<(int)((tot4 + 255) / 256), 256>>>(h_next, h_out, NH, stats,
                                                         stats + HDIM, gamma, beta);
        }
        {
            size_t tot4 = (size_t)NF * (HDIM / 4);
            bn_apply<<<(int)((tot4 + 255) / 256), 256>>>(f_next, f_out, NF, stats + 2 * HDIM,
                                                         stats + 3 * HDIM, gamma, beta);
        }

        h_cur = h_next;
        f_cur = f_next;
    }
}

// round 15
// speedup vs baseline: 1.6488x; 1.6488x over previous
#include <cuda_runtime.h>
#include <mma.h>
#include <cstdint>
#include <cstddef>

using namespace nvcuda;

#define NH 50000
#define NF 200000
#define HDIM 128
#define NUM_BLOCKS 2
#define TILE 2048

#define E_SENDS_MAX 1000000
#define E_PREC_MAX  2000000

// ---------------- scratch (device globals; no allocations allowed) ----------------
__device__ float g_agg_f0[(size_t)NF * HDIM];
__device__ float g_agg_f1[(size_t)NF * HDIM];
__device__ float g_agg_h0[(size_t)NH * HDIM];
__device__ float g_agg_h1[(size_t)NH * HDIM];
__device__ float g_f_buf1[(size_t)NF * HDIM];
__device__ float g_f_buf2[(size_t)NF * HDIM];
__device__ float g_h_buf1[(size_t)NH * HDIM];
__device__ float g_h_buf2[(size_t)NH * HDIM];
__device__ float g_Bt[2 * 2 * 128 * 384];       // [blk][type][n=128][k=384] K-major
__device__ float g_stats[4 * HDIM];             // [h: sum,sq][f: sum,sq]

// CSR scratch. deg4/next4 concatenated: [sends NF][prec NF][rev NH][reach NH].
// INVARIANT: deg4 all-zero at entry (zero-init at load; re-zeroed by scan_fix).
__device__ int g_deg4[2 * NF + 2 * NH];
__device__ int g_next4[2 * NF + 2 * NH];
__device__ int g_ptr_sends[NF + 1];
__device__ int g_ptr_prec[NF + 1];
__device__ int g_ptr_rev[NH + 1];
__device__ int g_ptr_reach[NH + 1];
__device__ int g_part[4 * 128];
__device__ int g_col_sends[E_SENDS_MAX];
__device__ int g_col_prec[E_PREC_MAX];
__device__ int g_col_rev[E_SENDS_MAX];
__device__ int g_col_reach[E_SENDS_MAX];

// ---------------- cache-hinted accessors ----------------
__device__ __forceinline__ void stcs4(float* p, float4 v) {
    asm volatile("st.global.cs.v4.f32 [%0], {%1,%2,%3,%4};"
                 :: "l"(p), "f"(v.x), "f"(v.y), "f"(v.z), "f"(v.w) : "memory");
}
__device__ __forceinline__ float4 ldcs4(const float* p) {
    float4 v;
    asm volatile("ld.global.cs.v4.f32 {%0,%1,%2,%3}, [%4];"
                 : "=f"(v.x), "=f"(v.y), "=f"(v.z), "=f"(v.w) : "l"(p));
    return v;
}
__device__ __forceinline__ float ldcs1(const float* p) {
    float v;
    asm volatile("ld.global.cs.f32 %0, [%1];" : "=f"(v) : "l"(p));
    return v;
}

__device__ __forceinline__ int type_n(int t) { return (t < 2) ? NF : NH; }
__device__ __forceinline__ int type_off(int t) {
    return (t == 0) ? 0 : (t == 1) ? NF : (t == 2) ? 2 * NF : 2 * NF + NH;
}

// ---------------- CSR build (4 launches; all types via blockIdx.y) ----------------

__global__ void hist_all(const int* __restrict__ e0, int E0, const int* __restrict__ e1, int E1,
                         const int* __restrict__ e2, int E2, const int* __restrict__ e3, int E3,
                         int* __restrict__ deg4) {
    int t = blockIdx.y;
    const int* ei = (t == 0) ? e0 : (t == 1) ? e1 : (t == 2) ? e2 : e3;
    int E = (t == 0) ? E0 : (t == 1) ? E1 : (t == 2) ? E2 : E3;
    int e = blockIdx.x * blockDim.x + threadIdx.x;
    if (e < E) atomicAdd(&deg4[type_off(t) + ei[E + e]], 1);
}

__global__ void scan_tiles(const int* __restrict__ deg4,
                           int* __restrict__ p0, int* __restrict__ p1,
                           int* __restrict__ p2, int* __restrict__ p3,
                           int* __restrict__ part) {
    int t = blockIdx.y;
    int n = type_n(t);
    int tiles = (n + TILE - 1) / TILE;
    if ((int)blockIdx.x >= tiles) return;
    const int* deg = deg4 + type_off(t);
    int* ptr = (t == 0) ? p0 : (t == 1) ? p1 : (t == 2) ? p2 : p3;
    __shared__ int sh[16];
    int base = blockIdx.x * TILE + threadIdx.x * 8;
    int v[8];
    int ls = 0;
#pragma unroll
    for (int j = 0; j < 8; j++) { v[j] = (base + j < n) ? deg[base + j] : 0; ls += v[j]; }
    int lane = threadIdx.x & 31, wid = threadIdx.x >> 5;
    int s = ls;
#pragma unroll
    for (int d = 1; d < 32; d <<= 1) {
        int x = __shfl_up_sync(0xffffffff, s, d);
        if (lane >= d) s += x;
    }
    if (lane == 31) sh[wid] = s;
    __syncthreads();
    if (threadIdx.x == 0) {
        int run = 0;
        for (int i = 0; i < 8; i++) { int x = sh[i]; sh[i] = run; run += x; }
        sh[8] = run;
    }
    __syncthreads();
    int run = sh[wid] + s - ls;
#pragma unroll
    for (int j = 0; j < 8; j++) {
        if (base + j < n) ptr[base + j] = run;
        run += v[j];
    }
    if (threadIdx.x == 0) part[t * 128 + blockIdx.x] = sh[8];
}

__global__ void scan_fix(int* __restrict__ p0, int* __restrict__ p1,
                         int* __restrict__ p2, int* __restrict__ p3,
                         int* __restrict__ next4, const int* __restrict__ part,
                         int* __restrict__ deg4) {
    int t = blockIdx.y;
    int n = type_n(t);
    int tiles = (n + TILE - 1) / TILE;
    if ((int)blockIdx.x >= tiles) return;
    int* ptr = (t == 0) ? p0 : (t == 1) ? p1 : (t == 2) ? p2 : p3;
    int* nxt = next4 + type_off(t);

    __shared__ int spart[128];
    __shared__ int s_off, s_tot;
    if (threadIdx.x < 128)
        spart[threadIdx.x] = (threadIdx.x < tiles) ? part[t * 128 + threadIdx.x] : 0;
    __syncthreads();
    if (threadIdx.x == 0) {
        int off = 0, tot = 0;
        for (int i = 0; i < tiles; i++) {
            if (i < (int)blockIdx.x) off += spart[i];
            tot += spart[i];
        }
        s_off = off; s_tot = tot;
    }
    __syncthreads();
    int off = s_off;

    int base = blockIdx.x * TILE + threadIdx.x * 8;
#pragma unroll
    for (int j = 0; j < 8; j++) {
        int idx = base + j;
        if (idx < n) {
            int v = ptr[idx] + off;
            ptr[idx] = v;
            nxt[idx] = v;
            deg4[type_off(t) + idx] = 0;
        }
    }
    if (blockIdx.x == 0 && threadIdx.x == 0) ptr[n] = s_tot;
}

__global__ void fill_all(const int* __restrict__ e0, int E0, const int* __restrict__ e1, int E1,
                         const int* __restrict__ e2, int E2, const int* __restrict__ e3, int E3,
                         int* __restrict__ next4,
                         int* __restrict__ c0, int* __restrict__ c1,
                         int* __restrict__ c2, int* __restrict__ c3) {
    int t = blockIdx.y;
    const int* ei = (t == 0) ? e0 : (t == 1) ? e1 : (t == 2) ? e2 : e3;
    int E = (t == 0) ? E0 : (t == 1) ? E1 : (t == 2) ? E2 : E3;
    int* col = (t == 0) ? c0 : (t == 1) ? c1 : (t == 2) ? c2 : c3;
    int* nxt = next4 + type_off(t);
    int e = blockIdx.x * blockDim.x + threadIdx.x;
    if (e >= E) return;
    int s = ei[e];
    int d = ei[E + e];
    int pos = atomicAdd(&nxt[d], 1);
    col[pos] = s;
}

// ---------------- gather-aggregate: warp per dst, mean folded in ----------------
__device__ __forceinline__ void gather_row(const float* __restrict__ src,
                                           const int* __restrict__ ptr,
                                           const int* __restrict__ col,
                                           int w, int lane, float* __restrict__ agg) {
    const int s0 = __ldg(&ptr[w]);
    const int s1 = __ldg(&ptr[w + 1]);
    float4 a0 = make_float4(0.f, 0.f, 0.f, 0.f);
    float4 a1 = make_float4(0.f, 0.f, 0.f, 0.f);
    float4 a2 = make_float4(0.f, 0.f, 0.f, 0.f);
    float4 a3 = make_float4(0.f, 0.f, 0.f, 0.f);
    int e = s0;
    for (; e + 3 < s1; e += 4) {
        int iA = __ldg(&col[e]);
        int iB = __ldg(&col[e + 1]);
        int iC = __ldg(&col[e + 2]);
        int iD = __ldg(&col[e + 3]);
        float4 vA = *(const float4*)(src + (size_t)iA * HDIM + lane * 4);
        float4 vB = *(const float4*)(src + (size_t)iB * HDIM + lane * 4);
        float4 vC = *(const float4*)(src + (size_t)iC * HDIM + lane * 4);
        float4 vD = *(const float4*)(src + (size_t)iD * HDIM + lane * 4);
        a0.x += vA.x; a0.y += vA.y; a0.z += vA.z; a0.w += vA.w;
        a1.x += vB.x; a1.y += vB.y; a1.z += vB.z; a1.w += vB.w;
        a2.x += vC.x; a2.y += vC.y; a2.z += vC.z; a2.w += vC.w;
        a3.x += vD.x; a3.y += vD.y; a3.z += vD.z; a3.w += vD.w;
    }
    for (; e < s1; e++) {
        int iA = __ldg(&col[e]);
        float4 vA = *(const float4*)(src + (size_t)iA * HDIM + lane * 4);
        a0.x += vA.x; a0.y += vA.y; a0.z += vA.z; a0.w += vA.w;
    }
    float inv = 1.0f / (float)max(s1 - s0, 1);
    float4 r;
    r.x = (a0.x + a1.x + a2.x + a3.x) * inv;
    r.y = (a0.y + a1.y + a2.y + a3.y) * inv;
    r.z = (a0.z + a1.z + a2.z + a3.z) * inv;
    r.w = (a0.w + a1.w + a2.w + a3.w) * inv;
    stcs4(agg + (size_t)w * HDIM + lane * 4, r);
}

// All four gathers in ONE launch: warps [0,NF) do flow dsts, [NF,NF+NH) host dsts.
__global__ __launch_bounds__(256) void gather_quad(
    const float* __restrict__ sA0, const int* __restrict__ pA0,
    const int* __restrict__ cA0, float* __restrict__ aA0,
    const float* __restrict__ sA1, const int* __restrict__ pA1,
    const int* __restrict__ cA1, float* __restrict__ aA1, int nA,
    const float* __restrict__ sB0, const int* __restrict__ pB0,
    const int* __restrict__ cB0, float* __restrict__ aB0,
    const float* __restrict__ sB1, const int* __restrict__ pB1,
    const int* __restrict__ cB1, float* __restrict__ aB1, int nB)
{
    const int w = (blockIdx.x * blockDim.x + threadIdx.x) >> 5;
    const int lane = threadIdx.x & 31;
    if (w < nA) {
        gather_row(sA0, pA0, cA0, w, lane, aA0);
        gather_row(sA1, pA1, cA1, w, lane, aA1);
    } else if (w < nA + nB) {
        int v = w - nA;
        gather_row(sB0, pB0, cB0, v, lane, aB0);
        gather_row(sB1, pB1, cB1, v, lane, aB1);
    }
}

// ---------------- weights ----------------
__global__ void prep_weights(const float* __restrict__ Wl, const float* __restrict__ Wr,
                             float* __restrict__ Bt) {
    int i = blockIdx.x * blockDim.x + threadIdx.x;
    const int total = 2 * 2 * 128 * 384;
    if (i >= total) return;
    int k = i % 384;
    int n = (i / 384) & 127;
    int t = (i / (384 * 128)) & 1;
    int b = i / (384 * 128 * 2);
    int ta = t ? 1 : 0, tb = t ? 3 : 2;
    int seg = k >> 7, kk = k & 127;
    float v;
    if (seg == 0)      v = Wl[(((size_t)b * 4 + ta) * 128 + n) * 128 + kk];
    else if (seg == 1) v = Wl[(((size_t)b * 4 + tb) * 128 + n) * 128 + kk];
    else               v = Wr[(((size_t)b * 4 + ta) * 128 + n) * 128 + kk]
                         + Wr[(((size_t)b * 4 + tb) * 128 + n) * 128 + kk];
    Bt[i] = 0.5f * v;
}

// ---------------- WMMA tf32 GEMM ----------------
__global__ __launch_bounds__(256) void gemm_wmma(
    const float* __restrict__ A0, const float* __restrict__ A1, const float* __restrict__ A2,
    const float* __restrict__ Bt, float* __restrict__ out, int nrows)
{
    __shared__ float Bs[128 * 36];
    const int tid = threadIdx.x;
    const int wid = tid >> 5;
    const int wrow = blockIdx.x * 128 + wid * 16;
    const bool wvalid = wrow < nrows;

    wmma::fragment<wmma::accumulator, 16, 16, 8, float> acc[8];
#pragma unroll
    for (int nt = 0; nt < 8; nt++) wmma::fill_fragment(acc[nt], 0.0f);

    for (int chunk = 0; chunk < 12; chunk++) {
        const float* Asrc = (chunk < 4) ? A0 : (chunk < 8) ? A1 : A2;
        const int kbase = chunk * 32;
        const int koff = (chunk & 3) * 32;

#pragma unroll
        for (int i = 0; i < 4; i++) {
            int idx = tid + i * 256;
            int n = idx >> 3, q = idx & 7;
            *(float4*)&Bs[n * 36 + q * 4] =
                *(const float4*)(Bt + (size_t)n * 384 + kbase + q * 4);
        }
        __syncthreads();

        if (wvalid) {
#pragma unroll
            for (int kk = 0; kk < 4; kk++) {
                wmma::fragment<wmma::matrix_a, 16, 16, 8, wmma::precision::tf32,
                               wmma::row_major> a;
                wmma::load_matrix_sync(a, Asrc + (size_t)wrow * HDIM + koff + kk * 8, HDIM);
#pragma unroll
                for (int t = 0; t < a.num_elements; t++)
                    a.x[t] = wmma::__float_to_tf32(a.x[t]);
#pragma unroll
                for (int nt = 0; nt < 8; nt++) {
                    wmma::fragment<wmma::matrix_b, 16, 16, 8, wmma::precision::tf32,
                                   wmma::col_major> b;
                    wmma::load_matrix_sync(b, Bs + nt * 16 * 36 + kk * 8, 36);
#pragma unroll
                    for (int t = 0; t < b.num_elements; t++)
                        b.x[t] = wmma::__float_to_tf32(b.x[t]);
                    wmma::mma_sync(acc[nt], a, b, acc[nt]);
                }
            }
        }
        __syncthreads();
    }

    if (wvalid) {
#pragma unroll
        for (int nt = 0; nt < 8; nt++)
            wmma::store_matrix_sync(out + (size_t)wrow * HDIM + nt * 16, acc[nt],
                                    HDIM, wmma::mem_row_major);
    }
}

// ---------------- BN + LeakyReLU (h and f merged via blockIdx.y) ----------------
__global__ void bn_stats2(const float* __restrict__ vh, const float* __restrict__ vf,
                          float* __restrict__ stats) {
    int t = blockIdx.y;                       // 0: h, 1: f
    const float* v = t ? vf : vh;
    int n = t ? NF : NH;
    float* sum = stats + t * 2 * HDIM;
    float* sq  = sum + HDIM;
    int c = threadIdx.x & 127;
    int sub = threadIdx.x >> 7;
    float s = 0.f, s2 = 0.f;
    for (int r = blockIdx.x * 2 + sub; r < n; r += gridDim.x * 2) {
        float x = ldcs1(v + (size_t)r * HDIM + c);
        s += x;
        s2 += x * x;
    }
    __shared__ float sh[256], sh2[256];
    sh[threadIdx.x] = s;
    sh2[threadIdx.x] = s2;
    __syncthreads();
    if (sub == 0) {
        atomicAdd(&sum[c], sh[c] + sh[c + 128]);
        atomicAdd(&sq[c], sh2[c] + sh2[c + 128]);
    }
}

__global__ void bn_apply2(const float* __restrict__ inh, float* __restrict__ outh,
                          const float* __restrict__ inf, float* __restrict__ outf,
                          const float* __restrict__ stats,
                          const float* __restrict__ gamma, const float* __restrict__ beta) {
    int t = blockIdx.y;
    const float* in = t ? inf : inh;
    float* out = t ? outf : outh;
    int n = t ? NF : NH;
    const float* sum = stats + t * 2 * HDIM;
    const float* sq  = sum + HDIM;
    size_t i4 = (size_t)blockIdx.x * blockDim.x + threadIdx.x;
    size_t total4 = (size_t)n * (HDIM / 4);
    if (i4 >= total4) return;
    int c4 = (int)(i4 & 31);
    float N = (float)n;
    float4 v = ldcs4(in + i4 * 4);
    float o[4];
#pragma unroll
    for (int j = 0; j < 4; j++) {
        int c = c4 * 4 + j;
        float mu = sum[c] / N;
        float var = sq[c] / N - mu * mu;
        float rstd = rsqrtf(var + 1e-5f);
        float x = (((&v.x)[j]) - mu) * rstd * gamma[c] + beta[c];
        o[j] = x >= 0.f ? x : 0.01f * x;
    }
    *(float4*)(out + i4 * 4) = make_float4(o[0], o[1], o[2], o[3]);
}

// ---------------- host ----------------
static inline void* sym(const void* s) {
    void* p = 0;
    cudaGetSymbolAddress(&p, s);
    return p;
}

extern "C" void kernel_launch(void* const* d_in, const int* in_sizes, int n_in,
                              void* d_out, int out_size) {
    const float* x_host = (const float*)d_in[0];
    const float* x_flow = (const float*)d_in[1];
    const int* ei_sends = (const int*)d_in[2];
    const int* ei_rev   = (const int*)d_in[3];
    const int* ei_prec  = (const int*)d_in[4];
    const int* ei_reach = (const int*)d_in[5];
    const float* W_l = (const float*)d_in[6];
    const float* W_r = (const float*)d_in[8];
    const float* bn_gamma = (const float*)d_in[9];
    const float* bn_beta  = (const float*)d_in[10];
    float* out = (float*)d_out;

    int E_sends = in_sizes[2] / 2;
    int E_rev   = in_sizes[3] / 2;
    int E_prec  = in_sizes[4] / 2;
    int E_reach = in_sizes[5] / 2;

    float* agg_f0 = (float*)sym(g_agg_f0);
    float* agg_f1 = (float*)sym(g_agg_f1);
    float* agg_h0 = (float*)sym(g_agg_h0);
    float* agg_h1 = (float*)sym(g_agg_h1);
    float* f_buf1 = (float*)sym(g_f_buf1);
    float* f_buf2 = (float*)sym(g_f_buf2);
    float* h_buf1 = (float*)sym(g_h_buf1);
    float* h_buf2 = (float*)sym(g_h_buf2);
    float* Bt    = (float*)sym(g_Bt);
    float* stats = (float*)sym(g_stats);

    int* deg4      = (int*)sym(g_deg4);
    int* next4     = (int*)sym(g_next4);
    int* ptr_sends = (int*)sym(g_ptr_sends);
    int* ptr_prec  = (int*)sym(g_ptr_prec);
    int* ptr_rev   = (int*)sym(g_ptr_rev);
    int* ptr_reach = (int*)sym(g_ptr_reach);
    int* part      = (int*)sym(g_part);
    int* col_sends = (int*)sym(g_col_sends);
    int* col_prec  = (int*)sym(g_col_prec);
    int* col_rev   = (int*)sym(g_col_rev);
    int* col_reach = (int*)sym(g_col_reach);

    // ---- CSR build: 4 launches (deg4 zero on entry; scan_fix restores it) ----
    int Emax = max(max(E_sends, E_prec), max(E_rev, E_reach));
    dim3 egrid((Emax + 255) / 256, 4);
    dim3 sgrid((NF + TILE - 1) / TILE, 4);

    hist_all<<<egrid, 256>>>(ei_sends, E_sends, ei_prec, E_prec,
                             ei_rev, E_rev, ei_reach, E_reach, deg4);
    scan_tiles<<<sgrid, 256>>>(deg4, ptr_sends, ptr_prec, ptr_rev, ptr_reach, part);
    scan_fix<<<sgrid, 256>>>(ptr_sends, ptr_prec, ptr_rev, ptr_reach, next4, part, deg4);
    fill_all<<<egrid, 256>>>(ei_sends, E_sends, ei_prec, E_prec,
                             ei_rev, E_rev, ei_reach, E_reach, next4,
                             col_sends, col_prec, col_rev, col_reach);

    const int gemm_grid_f = (NF + 127) / 128;
    const int gemm_grid_h = (NH + 127) / 128;
    const int gat_grid = ((NF + NH) * 32 + 255) / 256;

    const float* h_cur = x_host;
    const float* f_cur = x_flow;
    bool weights_done = false;

    for (int blk = 0; blk < NUM_BLOCKS; blk++) {
        float* f_next = blk == 0 ? f_buf1 : f_buf2;
        float* h_next = blk == 0 ? h_buf1 : h_buf2;

        // all four gathers in one launch (flow dsts then host dsts)
        gather_quad<<<gat_grid, 256>>>(h_cur, ptr_sends, col_sends, agg_f0,
                                       f_cur, ptr_prec, col_prec, agg_f1, NF,
                                       f_cur, ptr_rev, col_rev, agg_h0,
                                       f_cur, ptr_reach, col_reach, agg_h1, NH);

        if (!weights_done) {
            int tot = 2 * 2 * 128 * 384;
            prep_weights<<<(tot + 255) / 256, 256>>>(W_l, W_r, Bt);
            weights_done = true;
        }

        const float* Bf = Bt + (size_t)(blk * 2 + 0) * 128 * 384;
        const float* Bh = Bt + (size_t)(blk * 2 + 1) * 128 * 384;
        gemm_wmma<<<gemm_grid_f, 256>>>(agg_f0, agg_f1, f_cur, Bf, f_next, NF);
        gemm_wmma<<<gemm_grid_h, 256>>>(agg_h0, agg_h1, h_cur, Bh, h_next, NH);

        cudaMemsetAsync(stats, 0, 4 * HDIM * 4);
        {
            dim3 g(1024, 2);
            bn_stats2<<<g, 256>>>(h_next, f_next, stats);
        }

        const float* gamma = bn_gamma + blk * HDIM;
        const float* beta  = bn_beta + blk * HDIM;
        float* h_out = (blk == NUM_BLOCKS - 1) ? out : h_next;
        float* f_out = (blk == NUM_BLOCKS - 1) ? (out + (size_t)NH * HDIM) : f_next;
        {
            size_t tot4 = (size_t)NF * (HDIM / 4);
            dim3 g((unsigned)((tot4 + 255) / 256), 2);
            bn_apply2<<<g, 256>>>(h_next, h_out, f_next, f_out, stats, gamma, beta);
        }

        h_cur = h_next;
        f_cur = f_next;
    }
}